// round 7
// baseline (speedup 1.0000x reference)
#include <cuda_runtime.h>
#include <math.h>

#define LL 4
#define BB 8
#define NS 1200
#define NL 128
#define CC 768
#define HH 448
#define WW 448
#define GS 56            // 448/8
#define GL 16            // 448/28
#define NWARP_S (LL*BB*NS)   // 38400
#define NWARP_L (LL*BB*NL)   // 4096
#define CHUNK_S 240          // 1200 = 5 * 240
#define NCHUNK_S 5
#define NBLK_STATS (LL*BB*NCHUNK_S + LL*BB)   // 160 + 32 = 192

// Scratch (no allocation allowed)
__device__ float         g_d_s[NWARP_S];
__device__ float         g_d_l[NWARP_L];
__device__ unsigned char g_nzT_s[LL*NS*BB];   // [l][n][b] -> 8B aligned per (l,n)
__device__ unsigned char g_nzT_l[LL*NL*BB];
__device__ float g_sp[NBLK_STATS], g_sn[NBLK_STATS];
__device__ int   g_cp[NBLK_STATS], g_cn[NBLK_STATS];

// ---------------------------------------------------------------------------
// Kernel 1: per-row distance + nonzero flag (R3 layout — best measured).
// One warp per (l,b,n) row; 6 streaming float4 loads issued first (__ldcs).
__global__ void __launch_bounds__(256) dist_fused(const float* __restrict__ sel_s,
                                                  const float* __restrict__ ker_s,
                                                  const float* __restrict__ sel_l,
                                                  const float* __restrict__ ker_l) {
    // Let the dependent stats grid launch immediately (it pre-gathers its
    // independent inputs, then waits on full completion of this grid).
    cudaTriggerProgrammaticLaunchCompletion();

    int w    = blockIdx.x * 8 + (threadIdx.x >> 5);
    int lane = threadIdx.x & 31;

    const float* sel; const float* ker;
    float* dOut; unsigned char* nzT;
    int N, row;
    if (w < NWARP_S) {
        row = w; N = NS; sel = sel_s; ker = ker_s; dOut = g_d_s; nzT = g_nzT_s;
    } else {
        row = w - NWARP_S;
        if (row >= NWARP_L) return;
        N = NL; sel = sel_l; ker = ker_l; dOut = g_d_l; nzT = g_nzT_l;
    }
    int lb = row / N, n = row % N;
    int l = lb / BB, b = lb % BB;

    const float4* s4 = reinterpret_cast<const float4*>(sel) + (size_t)row * (CC/4);
    const float4* k4 = reinterpret_cast<const float4*>(ker) + (size_t)lb  * (CC/4);

    float4 sv[6], kv[6];
    #pragma unroll
    for (int i = 0; i < 6; i++) sv[i] = __ldcs(&s4[lane + 32*i]);   // streaming DRAM
    #pragma unroll
    for (int i = 0; i < 6; i++) kv[i] = __ldg(&k4[lane + 32*i]);    // L1/L2-resident

    float acc = 0.f;
    unsigned orb = 0u;
    #pragma unroll
    for (int i = 0; i < 6; i++) {
        float d0 = kv[i].x - sv[i].x, d1 = kv[i].y - sv[i].y;
        float d2 = kv[i].z - sv[i].z, d3 = kv[i].w - sv[i].w;
        acc = fmaf(d0, d0, acc); acc = fmaf(d1, d1, acc);
        acc = fmaf(d2, d2, acc); acc = fmaf(d3, d3, acc);
        orb |= __float_as_uint(sv[i].x) | __float_as_uint(sv[i].y)
             | __float_as_uint(sv[i].z) | __float_as_uint(sv[i].w);
    }
    #pragma unroll
    for (int o = 16; o; o >>= 1) {
        acc += __shfl_xor_sync(0xffffffffu, acc, o);
        orb |= __shfl_xor_sync(0xffffffffu, orb, o);
    }
    if (lane == 0) {
        dOut[row] = sqrtf(acc);
        nzT[(size_t)(l*N + n)*BB + b] = ((orb & 0x7fffffffu) != 0u) ? 1 : 0;
    }
}

// ---------------------------------------------------------------------------
// Kernel 2: partial masked sums. PDL secondary: pre-gathers idx + f_k
// membership (independent of dist), THEN waits for dist, then reads the
// (L2-hot) d / nz arrays.
__global__ void __launch_bounds__(256) stats_partial(const int* __restrict__ idx_s,
                                                     const int* __restrict__ idx_l,
                                                     const float* __restrict__ fk) {
    cudaTriggerProgrammaticLaunchCompletion();   // let final_kernel launch early

    int blk = blockIdx.x;
    bool is_s = blk < LL*BB*NCHUNK_S;
    int g, n0, nCnt;
    if (is_s) { g = blk / NCHUNK_S; n0 = (blk % NCHUNK_S) * CHUNK_S; nCnt = CHUNK_S; }
    else      { g = blk - LL*BB*NCHUNK_S; n0 = 0; nCnt = NL; }
    int l = g / BB, b = g % BB;

    int t = (int)threadIdx.x;
    bool live = (t < nCnt);
    int n = n0 + t;

    // ---- independent pre-work (overlaps with dist's tail) ----
    bool member = false;
    if (live) {
        int idx;
        if (is_s) {
            idx = idx_s[g*NS + n];
            int gy = idx / GS, gx = idx % GS;
            member = fk[(size_t)b*HH*WW + (size_t)gy*8*WW + gx*8] > 0.f;
        } else {
            idx = idx_l[g*NL + n];
            int gy = idx / GL, gx = idx % GL;
            member = fk[(size_t)b*HH*WW + (size_t)gy*28*WW + gx*28] > 0.f;
        }
    }

    // ---- wait for dist grid completion, then read its outputs ----
    cudaGridDependencySynchronize();

    float sp = 0.f, sn = 0.f;
    int cp = 0, cn = 0;
    if (live) {
        unsigned long long nz64;
        float d;
        if (is_s) {
            nz64 = *reinterpret_cast<const unsigned long long*>(g_nzT_s + (size_t)(l*NS + n)*8);
            d    = g_d_s[g*NS + n];
        } else {
            nz64 = *reinterpret_cast<const unsigned long long*>(g_nzT_l + (size_t)(l*NL + n)*8);
            d    = g_d_l[g*NL + n];
        }
        if (nz64 != 0ull) {
            if (member) { sp = d; cp = 1; } else { sn = d; cn = 1; }
        }
    }
    #pragma unroll
    for (int o = 16; o; o >>= 1) {
        sp += __shfl_xor_sync(0xffffffffu, sp, o);
        sn += __shfl_xor_sync(0xffffffffu, sn, o);
        cp += __shfl_xor_sync(0xffffffffu, cp, o);
        cn += __shfl_xor_sync(0xffffffffu, cn, o);
    }
    __shared__ float s_sp[8], s_sn[8];
    __shared__ int   s_cp[8], s_cn[8];
    int wid = t >> 5, ln = t & 31;
    if (ln == 0) { s_sp[wid] = sp; s_sn[wid] = sn; s_cp[wid] = cp; s_cn[wid] = cn; }
    __syncthreads();
    if (t == 0) {
        float tsp = 0.f, tsn = 0.f; int tcp = 0, tcn = 0;
        #pragma unroll
        for (int wI = 0; wI < 8; wI++) { tsp += s_sp[wI]; tsn += s_sn[wI]; tcp += s_cp[wI]; tcn += s_cn[wI]; }
        g_sp[blk] = tsp; g_sn[blk] = tsn; g_cp[blk] = tcp; g_cn[blk] = tcn;
    }
}

// ---------------------------------------------------------------------------
// Kernel 3: finish (PDL secondary of stats).
__global__ void final_kernel(float* __restrict__ out) {
    cudaGridDependencySynchronize();

    int t = (int)threadIdx.x;   // 0..63
    float sp = 0.f, sn = 0.f; int cp = 0, cn = 0;
    if (t < 32) {
        #pragma unroll
        for (int c = 0; c < NCHUNK_S; c++) {
            int s = t*NCHUNK_S + c;
            sp += g_sp[s]; sn += g_sn[s]; cp += g_cp[s]; cn += g_cn[s];
        }
    } else {
        int s = LL*BB*NCHUNK_S + (t - 32);
        sp = g_sp[s]; sn = g_sn[s]; cp = g_cp[s]; cn = g_cn[s];
    }
    float ap = sp / (float)max(cp, 1);
    float an = sn / (float)max(cn, 1);
    float x = ap - an;
    float loss = fmaxf(x, 0.f) + log1pf(expf(-fabsf(x)));   // stable softplus
    int act = (cp > 0 && cn > 0) ? 1 : 0;

    __shared__ float s_loss[64];
    __shared__ int   s_act[64];
    s_loss[t] = loss; s_act[t] = act;
    __syncthreads();
    if (t < 32) {
        int   as  = s_act[t];
        int   al  = s_act[32 + t] & as;        // act_l &= act_s
        float tot = (as ? s_loss[t] : 0.f) + (al ? s_loss[32 + t] : 0.f);
        int times = as + al;
        #pragma unroll
        for (int o = 16; o; o >>= 1) {
            tot   += __shfl_xor_sync(0xffffffffu, tot, o);
            times += __shfl_xor_sync(0xffffffffu, times, o);
        }
        if (t == 0) out[0] = (times > 0) ? tot / (float)times : 0.f;
    }
}

// ---------------------------------------------------------------------------
extern "C" void kernel_launch(void* const* d_in, const int* in_sizes, int n_in,
                              void* d_out, int out_size) {
    const float* sel_s = (const float*)d_in[0];
    const int*   idx_s = (const int*)  d_in[1];
    const float* sel_l = (const float*)d_in[2];
    const int*   idx_l = (const int*)  d_in[3];
    const float* ker_s = (const float*)d_in[4];
    const float* ker_l = (const float*)d_in[5];
    const float* fk    = (const float*)d_in[6];
    float* out = (float*)d_out;

    int nblk = (NWARP_S + NWARP_L + 7) / 8;   // 8 warps per 256-thread block
    dist_fused<<<nblk, 256>>>(sel_s, ker_s, sel_l, ker_l);

    cudaLaunchAttribute attr[1];
    attr[0].id = cudaLaunchAttributeProgrammaticStreamSerialization;
    attr[0].val.programmaticStreamSerializationAllowed = 1;

    {
        cudaLaunchConfig_t cfg = {};
        cfg.gridDim  = dim3(NBLK_STATS, 1, 1);
        cfg.blockDim = dim3(256, 1, 1);
        cfg.dynamicSmemBytes = 0;
        cfg.stream = 0;
        cfg.attrs = attr;
        cfg.numAttrs = 1;
        cudaLaunchKernelEx(&cfg, stats_partial, idx_s, idx_l, fk);
    }
    {
        cudaLaunchConfig_t cfg = {};
        cfg.gridDim  = dim3(1, 1, 1);
        cfg.blockDim = dim3(64, 1, 1);
        cfg.dynamicSmemBytes = 0;
        cfg.stream = 0;
        cfg.attrs = attr;
        cfg.numAttrs = 1;
        cudaLaunchKernelEx(&cfg, final_kernel, out);
    }
}

// round 8
// speedup vs baseline: 1.1883x; 1.1883x over previous
#include <cuda_runtime.h>
#include <math.h>

#define LL 4
#define BB 8
#define NS 1200
#define NL 128
#define CC 768
#define HH 448
#define WW 448
#define GS 56            // 448/8
#define GL 16            // 448/28
#define NWARP_S (LL*BB*NS)   // 38400 (divisible by 8)
#define NWARP_L (LL*BB*NL)   // 4096  (divisible by 8)
#define CHUNK_S 240          // 1200 = 5 * 240
#define NCHUNK_S 5
#define NBLK_STATS (LL*BB*NCHUNK_S + LL*BB)   // 160 + 32 = 192

// Scratch (no allocation allowed)
__device__ float         g_d_s[NWARP_S];
__device__ float         g_d_l[NWARP_L];
__device__ unsigned char g_nzT_s[LL*NS*BB];   // [l][n][b] -> 8B aligned per (l,n)
__device__ unsigned char g_nzT_l[LL*NL*BB];
__device__ float g_sp[NBLK_STATS], g_sn[NBLK_STATS];
__device__ int   g_cp[NBLK_STATS], g_cn[NBLK_STATS];

// ---------------------------------------------------------------------------
// Kernel 1: per-row distance + nonzero flag. One warp per row; a block's
// 8 rows always share lb (both 1200 and 128 divide by 8), so the kernel
// vector is staged in SMEM ONCE per block -> ker reads move off the L1tex
// LDG path (72 -> 48 wavefronts/warp).
__global__ void __launch_bounds__(256) dist_fused(const float* __restrict__ sel_s,
                                                  const float* __restrict__ ker_s,
                                                  const float* __restrict__ sel_l,
                                                  const float* __restrict__ ker_l) {
    __shared__ float4 s_ker[CC/4];   // 3 KB

    int w    = blockIdx.x * 8 + (threadIdx.x >> 5);
    int lane = threadIdx.x & 31;

    const float* sel; const float* ker;
    float* dOut; unsigned char* nzT;
    int N, row;
    bool live = true;
    if (w < NWARP_S) {
        row = w; N = NS; sel = sel_s; ker = ker_s; dOut = g_d_s; nzT = g_nzT_s;
    } else {
        row = w - NWARP_S;
        if (row >= NWARP_L) { live = false; row = 0; }
        N = NL; sel = sel_l; ker = ker_l; dOut = g_d_l; nzT = g_nzT_l;
    }
    int lb = row / N, n = row % N;
    int l = lb / BB, b = lb % BB;

    // Cooperative ker stage: 192 float4 loads by threads 0..191 (same lb for
    // the whole block). Issued before the streaming loads.
    if (threadIdx.x < CC/4) {
        const float4* kg = reinterpret_cast<const float4*>(ker) + (size_t)lb * (CC/4);
        s_ker[threadIdx.x] = __ldg(&kg[threadIdx.x]);
    }

    const float4* s4 = reinterpret_cast<const float4*>(sel) + (size_t)row * (CC/4);

    float4 sv[6];
    #pragma unroll
    for (int i = 0; i < 6; i++) sv[i] = __ldcs(&s4[lane + 32*i]);   // streaming DRAM

    __syncthreads();

    float acc = 0.f;
    unsigned orb = 0u;
    #pragma unroll
    for (int i = 0; i < 6; i++) {
        float4 kv = s_ker[lane + 32*i];                              // LDS.128, conflict-free
        float d0 = kv.x - sv[i].x, d1 = kv.y - sv[i].y;
        float d2 = kv.z - sv[i].z, d3 = kv.w - sv[i].w;
        acc = fmaf(d0, d0, acc); acc = fmaf(d1, d1, acc);
        acc = fmaf(d2, d2, acc); acc = fmaf(d3, d3, acc);
        orb |= __float_as_uint(sv[i].x) | __float_as_uint(sv[i].y)
             | __float_as_uint(sv[i].z) | __float_as_uint(sv[i].w);
    }
    #pragma unroll
    for (int o = 16; o; o >>= 1) {
        acc += __shfl_xor_sync(0xffffffffu, acc, o);
        orb |= __shfl_xor_sync(0xffffffffu, orb, o);
    }
    if (live && lane == 0) {
        dOut[row] = sqrtf(acc);
        nzT[(size_t)(l*N + n)*BB + b] = ((orb & 0x7fffffffu) != 0u) ? 1 : 0;
    }
}

// ---------------------------------------------------------------------------
// Kernel 2: partial masked sums (R3 version — known good).
__global__ void __launch_bounds__(256) stats_partial(const int* __restrict__ idx_s,
                                                     const int* __restrict__ idx_l,
                                                     const float* __restrict__ fk) {
    int blk = blockIdx.x;
    bool is_s = blk < LL*BB*NCHUNK_S;
    int g, n0, nCnt;
    if (is_s) { g = blk / NCHUNK_S; n0 = (blk % NCHUNK_S) * CHUNK_S; nCnt = CHUNK_S; }
    else      { g = blk - LL*BB*NCHUNK_S; n0 = 0; nCnt = NL; }
    int l = g / BB, b = g % BB;

    float sp = 0.f, sn = 0.f;
    int cp = 0, cn = 0;
    int t = (int)threadIdx.x;
    if (t < nCnt) {
        int n = n0 + t;
        unsigned long long nz64;
        float d; int idx; bool member;
        if (is_s) {
            nz64 = *reinterpret_cast<const unsigned long long*>(g_nzT_s + (size_t)(l*NS + n)*8);
            d    = g_d_s[g*NS + n];
            idx  = idx_s[g*NS + n];
            int gy = idx / GS, gx = idx % GS;
            member = fk[(size_t)b*HH*WW + (size_t)gy*8*WW + gx*8] > 0.f;
        } else {
            nz64 = *reinterpret_cast<const unsigned long long*>(g_nzT_l + (size_t)(l*NL + n)*8);
            d    = g_d_l[g*NL + n];
            idx  = idx_l[g*NL + n];
            int gy = idx / GL, gx = idx % GL;
            member = fk[(size_t)b*HH*WW + (size_t)gy*28*WW + gx*28] > 0.f;
        }
        if (nz64 != 0ull) {
            if (member) { sp = d; cp = 1; } else { sn = d; cn = 1; }
        }
    }
    #pragma unroll
    for (int o = 16; o; o >>= 1) {
        sp += __shfl_xor_sync(0xffffffffu, sp, o);
        sn += __shfl_xor_sync(0xffffffffu, sn, o);
        cp += __shfl_xor_sync(0xffffffffu, cp, o);
        cn += __shfl_xor_sync(0xffffffffu, cn, o);
    }
    __shared__ float s_sp[8], s_sn[8];
    __shared__ int   s_cp[8], s_cn[8];
    int wid = t >> 5, ln = t & 31;
    if (ln == 0) { s_sp[wid] = sp; s_sn[wid] = sn; s_cp[wid] = cp; s_cn[wid] = cn; }
    __syncthreads();
    if (t == 0) {
        float tsp = 0.f, tsn = 0.f; int tcp = 0, tcn = 0;
        #pragma unroll
        for (int wI = 0; wI < 8; wI++) { tsp += s_sp[wI]; tsn += s_sn[wI]; tcp += s_cp[wI]; tcn += s_cn[wI]; }
        g_sp[blk] = tsp; g_sn[blk] = tsn; g_cp[blk] = tcp; g_cn[blk] = tcn;
    }
}

// ---------------------------------------------------------------------------
// Kernel 3: finish (R3 version).
__global__ void final_kernel(float* __restrict__ out) {
    int t = (int)threadIdx.x;   // 0..63
    float sp = 0.f, sn = 0.f; int cp = 0, cn = 0;
    if (t < 32) {
        #pragma unroll
        for (int c = 0; c < NCHUNK_S; c++) {
            int s = t*NCHUNK_S + c;
            sp += g_sp[s]; sn += g_sn[s]; cp += g_cp[s]; cn += g_cn[s];
        }
    } else {
        int s = LL*BB*NCHUNK_S + (t - 32);
        sp = g_sp[s]; sn = g_sn[s]; cp = g_cp[s]; cn = g_cn[s];
    }
    float ap = sp / (float)max(cp, 1);
    float an = sn / (float)max(cn, 1);
    float x = ap - an;
    float loss = fmaxf(x, 0.f) + log1pf(expf(-fabsf(x)));   // stable softplus
    int act = (cp > 0 && cn > 0) ? 1 : 0;

    __shared__ float s_loss[64];
    __shared__ int   s_act[64];
    s_loss[t] = loss; s_act[t] = act;
    __syncthreads();
    if (t < 32) {
        int   as  = s_act[t];
        int   al  = s_act[32 + t] & as;        // act_l &= act_s
        float tot = (as ? s_loss[t] : 0.f) + (al ? s_loss[32 + t] : 0.f);
        int times = as + al;
        #pragma unroll
        for (int o = 16; o; o >>= 1) {
            tot   += __shfl_xor_sync(0xffffffffu, tot, o);
            times += __shfl_xor_sync(0xffffffffu, times, o);
        }
        if (t == 0) out[0] = (times > 0) ? tot / (float)times : 0.f;
    }
}

// ---------------------------------------------------------------------------
extern "C" void kernel_launch(void* const* d_in, const int* in_sizes, int n_in,
                              void* d_out, int out_size) {
    const float* sel_s = (const float*)d_in[0];
    const int*   idx_s = (const int*)  d_in[1];
    const float* sel_l = (const float*)d_in[2];
    const int*   idx_l = (const int*)  d_in[3];
    const float* ker_s = (const float*)d_in[4];
    const float* ker_l = (const float*)d_in[5];
    const float* fk    = (const float*)d_in[6];

    int nblk = (NWARP_S + NWARP_L) / 8;   // 5312, never straddles lb
    dist_fused<<<nblk, 256>>>(sel_s, ker_s, sel_l, ker_l);
    stats_partial<<<NBLK_STATS, 256>>>(idx_s, idx_l, fk);
    final_kernel<<<1, 64>>>((float*)d_out);
}

// round 10
// speedup vs baseline: 1.1995x; 1.0094x over previous
#include <cuda_runtime.h>
#include <math.h>

#define LL 4
#define BB 8
#define NS 1200
#define NL 128
#define CC 768
#define HH 448
#define WW 448
#define GS 56            // 448/8
#define GL 16            // 448/28
#define NWARP_S (LL*BB*NS)   // 38400 (divisible by 8)
#define NWARP_L (LL*BB*NL)   // 4096  (divisible by 8)
#define CHUNK_S 240          // 1200 = 5 * 240
#define NCHUNK_S 5
#define NBLK_STATS (LL*BB*NCHUNK_S + LL*BB)   // 160 + 32 = 192

// Scratch (no allocation allowed)
__device__ float         g_d_s[NWARP_S];
__device__ float         g_d_l[NWARP_L];
__device__ unsigned char g_nzT_s[LL*NS*BB];   // [l][n][b] -> 8B aligned per (l,n)
__device__ unsigned char g_nzT_l[LL*NL*BB];
__device__ float g_sp[NBLK_STATS], g_sn[NBLK_STATS];
__device__ int   g_cp[NBLK_STATS], g_cn[NBLK_STATS];

// ---------------------------------------------------------------------------
// Kernel 1: per-row distance + nonzero flag. One warp per row; a block's
// 8 rows always share lb, so the kernel vector is staged in SMEM once per
// block. __launch_bounds__(256, 6) forces 6 CTAs/SM (regs <= 42) now that
// the L1tex path is unclogged — more warps => more DRAM bytes in flight.
__global__ void __launch_bounds__(256, 6) dist_fused(const float* __restrict__ sel_s,
                                                     const float* __restrict__ ker_s,
                                                     const float* __restrict__ sel_l,
                                                     const float* __restrict__ ker_l) {
    __shared__ float4 s_ker[CC/4];   // 3 KB

    int w    = blockIdx.x * 8 + (threadIdx.x >> 5);
    int lane = threadIdx.x & 31;

    const float* sel; const float* ker;
    float* dOut; unsigned char* nzT;
    int N, row;
    bool live = true;
    if (w < NWARP_S) {
        row = w; N = NS; sel = sel_s; ker = ker_s; dOut = g_d_s; nzT = g_nzT_s;
    } else {
        row = w - NWARP_S;
        if (row >= NWARP_L) { live = false; row = 0; }
        N = NL; sel = sel_l; ker = ker_l; dOut = g_d_l; nzT = g_nzT_l;
    }
    int lb = row / N, n = row % N;
    int l = lb / BB, b = lb % BB;

    // Cooperative ker stage: 192 float4 loads by threads 0..191 (same lb for
    // the whole block). Issued before the streaming loads.
    if (threadIdx.x < CC/4) {
        const float4* kg = reinterpret_cast<const float4*>(ker) + (size_t)lb * (CC/4);
        s_ker[threadIdx.x] = __ldg(&kg[threadIdx.x]);
    }

    const float4* s4 = reinterpret_cast<const float4*>(sel) + (size_t)row * (CC/4);

    float4 sv[6];
    #pragma unroll
    for (int i = 0; i < 6; i++) sv[i] = __ldcs(&s4[lane + 32*i]);   // streaming DRAM

    __syncthreads();

    float acc = 0.f;
    unsigned orb = 0u;
    #pragma unroll
    for (int i = 0; i < 6; i++) {
        float4 kv = s_ker[lane + 32*i];                              // LDS.128, conflict-free
        float d0 = kv.x - sv[i].x, d1 = kv.y - sv[i].y;
        float d2 = kv.z - sv[i].z, d3 = kv.w - sv[i].w;
        acc = fmaf(d0, d0, acc); acc = fmaf(d1, d1, acc);
        acc = fmaf(d2, d2, acc); acc = fmaf(d3, d3, acc);
        orb |= __float_as_uint(sv[i].x) | __float_as_uint(sv[i].y)
             | __float_as_uint(sv[i].z) | __float_as_uint(sv[i].w);
    }
    #pragma unroll
    for (int o = 16; o; o >>= 1) {
        acc += __shfl_xor_sync(0xffffffffu, acc, o);
        orb |= __shfl_xor_sync(0xffffffffu, orb, o);
    }
    if (live && lane == 0) {
        dOut[row] = sqrtf(acc);
        nzT[(size_t)(l*N + n)*BB + b] = ((orb & 0x7fffffffu) != 0u) ? 1 : 0;
    }
}

// ---------------------------------------------------------------------------
// Kernel 2: partial masked sums (known good).
__global__ void __launch_bounds__(256) stats_partial(const int* __restrict__ idx_s,
                                                     const int* __restrict__ idx_l,
                                                     const float* __restrict__ fk) {
    int blk = blockIdx.x;
    bool is_s = blk < LL*BB*NCHUNK_S;
    int g, n0, nCnt;
    if (is_s) { g = blk / NCHUNK_S; n0 = (blk % NCHUNK_S) * CHUNK_S; nCnt = CHUNK_S; }
    else      { g = blk - LL*BB*NCHUNK_S; n0 = 0; nCnt = NL; }
    int l = g / BB, b = g % BB;

    float sp = 0.f, sn = 0.f;
    int cp = 0, cn = 0;
    int t = (int)threadIdx.x;
    if (t < nCnt) {
        int n = n0 + t;
        unsigned long long nz64;
        float d; int idx; bool member;
        if (is_s) {
            nz64 = *reinterpret_cast<const unsigned long long*>(g_nzT_s + (size_t)(l*NS + n)*8);
            d    = g_d_s[g*NS + n];
            idx  = idx_s[g*NS + n];
            int gy = idx / GS, gx = idx % GS;
            member = fk[(size_t)b*HH*WW + (size_t)gy*8*WW + gx*8] > 0.f;
        } else {
            nz64 = *reinterpret_cast<const unsigned long long*>(g_nzT_l + (size_t)(l*NL + n)*8);
            d    = g_d_l[g*NL + n];
            idx  = idx_l[g*NL + n];
            int gy = idx / GL, gx = idx % GL;
            member = fk[(size_t)b*HH*WW + (size_t)gy*28*WW + gx*28] > 0.f;
        }
        if (nz64 != 0ull) {
            if (member) { sp = d; cp = 1; } else { sn = d; cn = 1; }
        }
    }
    #pragma unroll
    for (int o = 16; o; o >>= 1) {
        sp += __shfl_xor_sync(0xffffffffu, sp, o);
        sn += __shfl_xor_sync(0xffffffffu, sn, o);
        cp += __shfl_xor_sync(0xffffffffu, cp, o);
        cn += __shfl_xor_sync(0xffffffffu, cn, o);
    }
    __shared__ float s_sp[8], s_sn[8];
    __shared__ int   s_cp[8], s_cn[8];
    int wid = t >> 5, ln = t & 31;
    if (ln == 0) { s_sp[wid] = sp; s_sn[wid] = sn; s_cp[wid] = cp; s_cn[wid] = cn; }
    __syncthreads();
    if (t == 0) {
        float tsp = 0.f, tsn = 0.f; int tcp = 0, tcn = 0;
        #pragma unroll
        for (int wI = 0; wI < 8; wI++) { tsp += s_sp[wI]; tsn += s_sn[wI]; tcp += s_cp[wI]; tcn += s_cn[wI]; }
        g_sp[blk] = tsp; g_sn[blk] = tsn; g_cp[blk] = tcp; g_cn[blk] = tcn;
    }
}

// ---------------------------------------------------------------------------
// Kernel 3: finish.
__global__ void final_kernel(float* __restrict__ out) {
    int t = (int)threadIdx.x;   // 0..63
    float sp = 0.f, sn = 0.f; int cp = 0, cn = 0;
    if (t < 32) {
        #pragma unroll
        for (int c = 0; c < NCHUNK_S; c++) {
            int s = t*NCHUNK_S + c;
            sp += g_sp[s]; sn += g_sn[s]; cp += g_cp[s]; cn += g_cn[s];
        }
    } else {
        int s = LL*BB*NCHUNK_S + (t - 32);
        sp = g_sp[s]; sn = g_sn[s]; cp = g_cp[s]; cn = g_cn[s];
    }
    float ap = sp / (float)max(cp, 1);
    float an = sn / (float)max(cn, 1);
    float x = ap - an;
    float loss = fmaxf(x, 0.f) + log1pf(expf(-fabsf(x)));   // stable softplus
    int act = (cp > 0 && cn > 0) ? 1 : 0;

    __shared__ float s_loss[64];
    __shared__ int   s_act[64];
    s_loss[t] = loss; s_act[t] = act;
    __syncthreads();
    if (t < 32) {
        int   as  = s_act[t];
        int   al  = s_act[32 + t] & as;        // act_l &= act_s
        float tot = (as ? s_loss[t] : 0.f) + (al ? s_loss[32 + t] : 0.f);
        int times = as + al;
        #pragma unroll
        for (int o = 16; o; o >>= 1) {
            tot   += __shfl_xor_sync(0xffffffffu, tot, o);
            times += __shfl_xor_sync(0xffffffffu, times, o);
        }
        if (t == 0) out[0] = (times > 0) ? tot / (float)times : 0.f;
    }
}

// ---------------------------------------------------------------------------
extern "C" void kernel_launch(void* const* d_in, const int* in_sizes, int n_in,
                              void* d_out, int out_size) {
    const float* sel_s = (const float*)d_in[0];
    const int*   idx_s = (const int*)  d_in[1];
    const float* sel_l = (const float*)d_in[2];
    const int*   idx_l = (const int*)  d_in[3];
    const float* ker_s = (const float*)d_in[4];
    const float* ker_l = (const float*)d_in[5];
    const float* fk    = (const float*)d_in[6];

    int nblk = (NWARP_S + NWARP_L) / 8;   // 5312, never straddles lb
    dist_fused<<<nblk, 256>>>(sel_s, ker_s, sel_l, ker_l);
    stats_partial<<<NBLK_STATS, 256>>>(idx_s, idx_l, fk);
    final_kernel<<<1, 64>>>((float*)d_out);
}